// round 9
// baseline (speedup 1.0000x reference)
#include <cuda_runtime.h>
#include <math.h>

#define B_  32
#define T0_ 2048
#define T1_ 2044
#define T2_ 2040
#define T3_ 2034

// ---------------- scratch (device globals; no allocations allowed) ----------
__device__ float g_xT  [20   * B_ * T0_];
__device__ float g_act1[512  * B_ * T1_];
__device__ float g_act2[512  * B_ * T2_];
__device__ float g_act3[512  * B_ * T3_];
__device__ float g_act4[512  * B_ * T3_];
__device__ float g_act5[1500 * B_ * T3_];
__device__ float g_scl [1500];
__device__ float g_shf [1500];
__device__ float g_wp  [512 * 1536];     // folded weights (max 786432 elems)
__device__ float g_bp  [1500];           // folded bias
__device__ float g_pool[B_ * 3000];
__device__ float g_y1  [B_ * 512];
__device__ float g_y2  [B_ * 512];

// ---------------- transpose x[b][t][f] -> xT[f][b][t] -----------------------
__global__ void transpose_x(const float* __restrict__ x, float* __restrict__ xT) {
    int idx = blockIdx.x * blockDim.x + threadIdx.x;
    const int total = B_ * T0_ * 20;
    if (idx >= total) return;
    int f = idx % 20;
    int t = (idx / 20) % T0_;
    int b = idx / (20 * T0_);
    xT[((size_t)f * B_ + b) * T0_ + t] = x[idx];
}

// ---------------- fold BN affine into weights --------------------------------
// Wp[m,k] = W[m,k]*scl[f(k)],  bp[m] = bias[m] + sum_k W[m,k]*shf[f(k)]
__global__ void prep_weights(const float* __restrict__ W, const float* __restrict__ bias,
                             const float* __restrict__ scl, const float* __restrict__ shf,
                             float* __restrict__ Wp, float* __restrict__ bp,
                             int M, int K, int C, int hasAff)
{
    int m    = blockIdx.x * (blockDim.x >> 5) + (threadIdx.x >> 5);
    int lane = threadIdx.x & 31;
    if (m >= M) return;
    float acc = 0.f;
    for (int k = lane; k < K; k += 32) {
        float w = W[(size_t)m * K + k];
        float sA = 1.f, sB = 0.f;
        if (hasAff) { int f = k / C; sA = scl[f]; sB = shf[f]; }
        Wp[(size_t)m * K + k] = w * sA;
        acc += w * sB;
    }
#pragma unroll
    for (int off = 16; off; off >>= 1) acc += __shfl_xor_sync(0xffffffffu, acc, off);
    if (lane == 0) bp[m] = bias[m] + acc;
}

// ---------------- TF32 helpers ----------------------------------------------
__device__ __forceinline__ unsigned f2tf32(float v) {
    unsigned r;
    asm("cvt.rna.tf32.f32 %0, %1;" : "=r"(r) : "f"(v));
    return r;
}
__device__ __forceinline__ void split_tf32(float v, unsigned &hi, unsigned &lo) {
    hi = f2tf32(v);
    lo = f2tf32(v - __uint_as_float(hi));
}

__device__ __forceinline__ void mma_tf32(float c[4],
                                         unsigned a0, unsigned a1, unsigned a2, unsigned a3,
                                         unsigned b0, unsigned b1) {
    asm("mma.sync.aligned.m16n8k8.row.col.f32.tf32.tf32.f32 "
        "{%0,%1,%2,%3}, {%4,%5,%6,%7}, {%8,%9}, {%0,%1,%2,%3};"
        : "+f"(c[0]), "+f"(c[1]), "+f"(c[2]), "+f"(c[3])
        : "r"(a0), "r"(a1), "r"(a2), "r"(a3), "r"(b0), "r"(b1));
}

// ---------------- fused splice + 1x1 conv GEMM (3xTF32, double-buffered) -----
// Block 128x128x16, 8 warps, warp tile 64x32. Raw fp32 in smem, split at
// fragment load. Reg-staged double buffer: one __syncthreads per k-tile.
#define TBM 128
#define TBN 128
#define TBK 16
#define PAD 8

__global__ __launch_bounds__(256, 2)
void gemm_splice(const float* __restrict__ W, const float* __restrict__ bias,
                 const float* __restrict__ X, float* __restrict__ Y,
                 int M, int K, int C, int offStride,
                 int Tin, int Tout, int actMode)
{
    __shared__ float As[2][TBK][TBM + PAD];
    __shared__ float Bs[2][TBK][TBN + PAD];

    const int b     = blockIdx.z;
    const int m0    = blockIdx.y * TBM;
    const int tbase = blockIdx.x * TBN;
    const int tid   = threadIdx.x;

    const int lane  = tid & 31;
    const int warp  = tid >> 5;
    const int g     = lane >> 2;
    const int tg    = lane & 3;
    const int wm    = (warp & 1) * 64;
    const int wn    = (warp >> 1) * 32;

    const float* Xb = X + (size_t)b * Tin;

    float acc[4][4][4];
#pragma unroll
    for (int mi = 0; mi < 4; mi++)
#pragma unroll
        for (int ni = 0; ni < 4; ni++)
#pragma unroll
            for (int r = 0; r < 4; r++) acc[mi][ni][r] = 0.f;

    const int aRow  = tid >> 1;
    const int aCol0 = (tid & 1) * 8;
    const int bRow  = tid >> 4;
    const int bCol0 = (tid & 15) * 8;
    const int mA_   = m0 + aRow;

    float aReg[8], bReg[8];

    auto loadT = [&](int k0) {
        const float* wsrc = W + (size_t)mA_ * K + k0 + aCol0;
#pragma unroll
        for (int j = 0; j < 8; j++) {
            int k = k0 + aCol0 + j;
            aReg[j] = (mA_ < M && k < K) ? wsrc[j] : 0.f;
        }
        int kB = k0 + bRow;
        bool kv = (kB < K);
        int f = 0, off = 0;
        if (kv) { f = kB / C; off = (kB - f * C) * offStride; }
        const float* src = Xb + (size_t)f * (B_ * (size_t)Tin) + off + tbase + bCol0;
#pragma unroll
        for (int j = 0; j < 8; j++) {
            int t = tbase + bCol0 + j;
            bReg[j] = (kv && t < Tout) ? src[j] : 0.f;
        }
    };
    auto storeT = [&](int buf) {
#pragma unroll
        for (int j = 0; j < 8; j++) As[buf][aCol0 + j][aRow] = aReg[j];
        *(float4*)&Bs[buf][bRow][bCol0]     = make_float4(bReg[0], bReg[1], bReg[2], bReg[3]);
        *(float4*)&Bs[buf][bRow][bCol0 + 4] = make_float4(bReg[4], bReg[5], bReg[6], bReg[7]);
    };

    const int nT = (K + TBK - 1) / TBK;
    loadT(0);
    storeT(0);
    __syncthreads();

    for (int it = 0; it < nT; it++) {
        const int buf = it & 1;
        if (it + 1 < nT) loadT((it + 1) * TBK);   // prefetch next tile (LDG early)

#pragma unroll
        for (int kk = 0; kk < TBK; kk += 8) {
            unsigned afh[4][4], afl[4][4], bfh[4][2], bfl[4][2];
#pragma unroll
            for (int mi = 0; mi < 4; mi++) {
                int m = wm + mi * 16 + g;
                float r0 = As[buf][kk + tg    ][m];
                float r1 = As[buf][kk + tg    ][m + 8];
                float r2 = As[buf][kk + tg + 4][m];
                float r3 = As[buf][kk + tg + 4][m + 8];
                split_tf32(r0, afh[mi][0], afl[mi][0]);
                split_tf32(r1, afh[mi][1], afl[mi][1]);
                split_tf32(r2, afh[mi][2], afl[mi][2]);
                split_tf32(r3, afh[mi][3], afl[mi][3]);
            }
#pragma unroll
            for (int ni = 0; ni < 4; ni++) {
                int n = wn + ni * 8 + g;
                float r0 = Bs[buf][kk + tg    ][n];
                float r1 = Bs[buf][kk + tg + 4][n];
                split_tf32(r0, bfh[ni][0], bfl[ni][0]);
                split_tf32(r1, bfh[ni][1], bfl[ni][1]);
            }
#pragma unroll
            for (int mi = 0; mi < 4; mi++)
#pragma unroll
                for (int ni = 0; ni < 4; ni++) {
                    mma_tf32(acc[mi][ni], afh[mi][0], afh[mi][1], afh[mi][2], afh[mi][3],
                             bfh[ni][0], bfh[ni][1]);
                    mma_tf32(acc[mi][ni], afh[mi][0], afh[mi][1], afh[mi][2], afh[mi][3],
                             bfl[ni][0], bfl[ni][1]);
                    mma_tf32(acc[mi][ni], afl[mi][0], afl[mi][1], afl[mi][2], afl[mi][3],
                             bfh[ni][0], bfh[ni][1]);
                }
        }

        if (it + 1 < nT) storeT(buf ^ 1);
        __syncthreads();
    }

    // ---- epilogue: bias + activation, write [M][B][Tout] ----
    const size_t strideY = (size_t)B_ * Tout;
#pragma unroll
    for (int mi = 0; mi < 4; mi++) {
        int mA = m0 + wm + mi * 16 + g;
        int mB = mA + 8;
        float biA = (mA < M) ? bias[mA] : 0.f;
        float biB = (mB < M) ? bias[mB] : 0.f;
#pragma unroll
        for (int ni = 0; ni < 4; ni++) {
            int t = tbase + wn + ni * 8 + tg * 2;
            if (t >= Tout) continue;
            if (mA < M) {
                float2 v;
                v.x = fmaxf(acc[mi][ni][0] + biA, 0.f);
                v.y = fmaxf(acc[mi][ni][1] + biA, 0.f);
                if (actMode) { v.x = fminf(v.x, 6.f); v.y = fminf(v.y, 6.f); }
                *(float2*)&Y[(size_t)mA * strideY + (size_t)b * Tout + t] = v;
            }
            if (mB < M) {
                float2 v;
                v.x = fmaxf(acc[mi][ni][2] + biB, 0.f);
                v.y = fmaxf(acc[mi][ni][3] + biB, 0.f);
                if (actMode) { v.x = fminf(v.x, 6.f); v.y = fminf(v.y, 6.f); }
                *(float2*)&Y[(size_t)mB * strideY + (size_t)b * Tout + t] = v;
            }
        }
    }
}

// ---------------- per-channel batch-norm stats (over B*T) -------------------
__global__ void channel_stats(const float* __restrict__ Y, int N,
                              const float* __restrict__ gam, const float* __restrict__ bet,
                              float* __restrict__ scl, float* __restrict__ shf)
{
    int c = blockIdx.x;
    const float4* p = (const float4*)(Y + (size_t)c * N);
    int n4 = N >> 2;
    float s1 = 0.f, s2 = 0.f;
    for (int i = threadIdx.x; i < n4; i += blockDim.x) {
        float4 v = p[i];
        s1 += v.x + v.y + v.z + v.w;
        s2 += v.x*v.x + v.y*v.y + v.z*v.z + v.w*v.w;
    }
    __shared__ float r1[256], r2[256];
    r1[threadIdx.x] = s1; r2[threadIdx.x] = s2;
    __syncthreads();
    for (int s = 128; s > 0; s >>= 1) {
        if (threadIdx.x < s) {
            r1[threadIdx.x] += r1[threadIdx.x + s];
            r2[threadIdx.x] += r2[threadIdx.x + s];
        }
        __syncthreads();
    }
    if (threadIdx.x == 0) {
        float m   = r1[0] / (float)N;
        float var = r2[0] / (float)N - m * m;
        float inv = rsqrtf(var + 1e-5f);
        float g   = gam ? gam[c] : 1.f;
        float be  = bet ? bet[c] : 0.f;
        float A   = g * inv;
        scl[c] = A;
        shf[c] = be - m * A;
    }
}

// ---------------- fused bn5 stats + pooled mean/std --------------------------
// One pass over a5: per-channel BN stats (over B*T) AND per-(c,b) time stats.
__global__ void stats_pool(const float* __restrict__ A,
                           const float* __restrict__ gam, const float* __restrict__ bet,
                           float* __restrict__ P)
{
    int c   = blockIdx.x;
    int tid = threadIdx.x;
    int bb  = tid >> 3;     // 0..31
    int sub = tid & 7;      // 0..7
    const float* p = A + ((size_t)c * B_ + bb) * T3_;
    float s1 = 0.f, s2 = 0.f;
    const int n2 = T3_ >> 1;   // 1017, exact (T3_ even)
    for (int i = sub; i < n2; i += 8) {
        float2 v = *(const float2*)(p + 2 * i);
        s1 += v.x + v.y;
        s2 += v.x * v.x + v.y * v.y;
    }
    __shared__ float r1[256], r2[256];
    r1[tid] = s1; r2[tid] = s2;
    __syncthreads();
    if (sub < 4) { r1[tid] += r1[tid + 4]; r2[tid] += r2[tid + 4]; }
    __syncthreads();
    if (sub < 2) { r1[tid] += r1[tid + 2]; r2[tid] += r2[tid + 2]; }
    __syncthreads();
    if (sub == 0) { r1[tid] += r1[tid + 1]; r2[tid] += r2[tid + 1]; }
    __syncthreads();
    __shared__ float shA, shD;
    if (tid == 0) {
        float t1 = 0.f, t2 = 0.f;
        for (int i = 0; i < 32; i++) { t1 += r1[i * 8]; t2 += r2[i * 8]; }
        float m   = t1 / (float)(B_ * T3_);
        float var = t2 / (float)(B_ * T3_) - m * m;
        float inv = rsqrtf(var + 1e-5f);
        float Aa  = gam[c] * inv;
        shA = Aa;
        shD = bet[c] - m * Aa;
    }
    __syncthreads();
    if (sub == 0) {
        float m   = r1[tid] / (float)T3_;
        float var = (r2[tid] - (float)T3_ * m * m) / (float)(T3_ - 1);
        P[bb * 3000 + c]        = shA * m + shD;
        P[bb * 3000 + 1500 + c] = fabsf(shA) * sqrtf(fmaxf(var, 0.f));
    }
}

// ---------------- dense + relu6 (one warp per output) -----------------------
__global__ void dense_relu6(const float* __restrict__ W, const float* __restrict__ bias,
                            const float* __restrict__ X, float* __restrict__ Y,
                            int M, int K)
{
    int gw   = (blockIdx.x * blockDim.x + threadIdx.x) >> 5;
    int lane = threadIdx.x & 31;
    if (gw >= B_ * M) return;
    int b = gw / M, o = gw - b * M;
    const float* w = W + (size_t)o * K;
    const float* x = X + (size_t)b * K;
    float s = 0.f;
    for (int k = lane; k < K; k += 32) s += w[k] * x[k];
#pragma unroll
    for (int off = 16; off; off >>= 1) s += __shfl_xor_sync(0xffffffffu, s, off);
    if (lane == 0) {
        float v = s + bias[o];
        Y[(size_t)b * M + o] = fminf(fmaxf(v, 0.f), 6.f);
    }
}

// ---------------- batch-norm over batch dim (B=32 == warp) ------------------
__global__ void bn_batch(const float* __restrict__ Y, const float* __restrict__ gam,
                         const float* __restrict__ bet, float* __restrict__ Out, int M)
{
    int o    = (blockIdx.x * blockDim.x + threadIdx.x) >> 5;
    int lane = threadIdx.x & 31;
    if (o >= M) return;
    float v  = Y[(size_t)lane * M + o];
    float s1 = v, s2 = v * v;
#pragma unroll
    for (int off = 16; off; off >>= 1) {
        s1 += __shfl_xor_sync(0xffffffffu, s1, off);
        s2 += __shfl_xor_sync(0xffffffffu, s2, off);
    }
    float m   = s1 * (1.f / 32.f);
    float var = s2 * (1.f / 32.f) - m * m;
    float r   = rsqrtf(var + 1e-5f);
    Out[(size_t)lane * M + o] = (v - m) * r * gam[o] + bet[o];
}

// ---------------- launch ----------------------------------------------------
extern "C" void kernel_launch(void* const* d_in, const int* in_sizes, int n_in,
                              void* d_out, int out_size)
{
    const float* x     = (const float*)d_in[0];
    const float* h1_w  = (const float*)d_in[1];
    const float* h1_b  = (const float*)d_in[2];
    const float* h2_w  = (const float*)d_in[3];
    const float* h2_b  = (const float*)d_in[4];
    const float* bn2_g = (const float*)d_in[5];
    const float* bn2_b = (const float*)d_in[6];
    const float* h3_w  = (const float*)d_in[7];
    const float* h3_b  = (const float*)d_in[8];
    const float* bn3_g = (const float*)d_in[9];
    const float* bn3_b = (const float*)d_in[10];
    const float* h4_w  = (const float*)d_in[11];
    const float* h4_b  = (const float*)d_in[12];
    const float* bn4_g = (const float*)d_in[13];
    const float* bn4_b = (const float*)d_in[14];
    const float* h5_w  = (const float*)d_in[15];
    const float* h5_b  = (const float*)d_in[16];
    const float* bn5_g = (const float*)d_in[17];
    const float* bn5_b = (const float*)d_in[18];
    const float* l1_w  = (const float*)d_in[19];
    const float* l1_b  = (const float*)d_in[20];
    const float* bn6_g = (const float*)d_in[21];
    const float* bn6_b = (const float*)d_in[22];
    const float* l2_w  = (const float*)d_in[23];
    const float* l2_b  = (const float*)d_in[24];
    const float* bn7_g = (const float*)d_in[25];
    const float* bn7_b = (const float*)d_in[26];

    float *xT, *a1, *a2, *a3, *a4, *a5, *scl, *shf, *wp, *bp, *pool, *y1, *y2;
    cudaGetSymbolAddress((void**)&xT,   g_xT);
    cudaGetSymbolAddress((void**)&a1,   g_act1);
    cudaGetSymbolAddress((void**)&a2,   g_act2);
    cudaGetSymbolAddress((void**)&a3,   g_act3);
    cudaGetSymbolAddress((void**)&a4,   g_act4);
    cudaGetSymbolAddress((void**)&a5,   g_act5);
    cudaGetSymbolAddress((void**)&scl,  g_scl);
    cudaGetSymbolAddress((void**)&shf,  g_shf);
    cudaGetSymbolAddress((void**)&wp,   g_wp);
    cudaGetSymbolAddress((void**)&bp,   g_bp);
    cudaGetSymbolAddress((void**)&pool, g_pool);
    cudaGetSymbolAddress((void**)&y1,   g_y1);
    cudaGetSymbolAddress((void**)&y2,   g_y2);

    const int N1 = B_ * T1_;
    const int N2 = B_ * T2_;
    const int N3 = B_ * T3_;

    transpose_x<<<(B_ * T0_ * 20 + 255) / 256, 256>>>(x, xT);

    // Layer 1: splice(0..4) + h1 + relu (no input affine)
    prep_weights<<<(512 + 7) / 8, 256>>>(h1_w, h1_b, nullptr, nullptr, wp, bp, 512, 100, 5, 0);
    gemm_splice<<<dim3((T1_ + 127) / 128, 4, B_), 256>>>(
        wp, bp, xT, a1, 512, 100, 5, 1, T0_, T1_, 0);
    channel_stats<<<512, 256>>>(a1, N1, nullptr, nullptr, scl, shf);

    // Layer 2: bn1 folded into weights; splice(0,2,4) + h2 + relu
    prep_weights<<<(512 + 7) / 8, 256>>>(h2_w, h2_b, scl, shf, wp, bp, 512, 1536, 3, 1);
    gemm_splice<<<dim3((T2_ + 127) / 128, 4, B_), 256>>>(
        wp, bp, a1, a2, 512, 1536, 3, 2, T1_, T2_, 0);
    channel_stats<<<512, 256>>>(a2, N2, bn2_g, bn2_b, scl, shf);

    // Layer 3: bn2 folded; splice(0,3,6) + h3 + relu
    prep_weights<<<(512 + 7) / 8, 256>>>(h3_w, h3_b, scl, shf, wp, bp, 512, 1536, 3, 1);
    gemm_splice<<<dim3((T3_ + 127) / 128, 4, B_), 256>>>(
        wp, bp, a2, a3, 512, 1536, 3, 3, T2_, T3_, 0);
    channel_stats<<<512, 256>>>(a3, N3, bn3_g, bn3_b, scl, shf);

    // Layer 4: bn3 folded; h4 + relu6
    prep_weights<<<(512 + 7) / 8, 256>>>(h4_w, h4_b, scl, shf, wp, bp, 512, 512, 1, 1);
    gemm_splice<<<dim3((T3_ + 127) / 128, 4, B_), 256>>>(
        wp, bp, a3, a4, 512, 512, 1, 0, T3_, T3_, 1);
    channel_stats<<<512, 256>>>(a4, N3, bn4_g, bn4_b, scl, shf);

    // Layer 5: bn4 folded; h5 + relu6
    prep_weights<<<(1500 + 7) / 8, 256>>>(h5_w, h5_b, scl, shf, wp, bp, 1500, 512, 1, 1);
    gemm_splice<<<dim3((T3_ + 127) / 128, 12, B_), 256>>>(
        wp, bp, a4, a5, 1500, 512, 1, 0, T3_, T3_, 1);

    // Fused bn5 stats + pooling -> [B, 3000]
    stats_pool<<<1500, 256>>>(a5, bn5_g, bn5_b, pool);

    dense_relu6<<<(B_ * 512 * 32 + 255) / 256, 256>>>(l1_w, l1_b, pool, y1, 512, 3000);
    bn_batch<<<(512 * 32 + 255) / 256, 256>>>(y1, bn6_g, bn6_b, y1, 512);

    dense_relu6<<<(B_ * 512 * 32 + 255) / 256, 256>>>(l2_w, l2_b, y1, y2, 512, 512);
    bn_batch<<<(512 * 32 + 255) / 256, 256>>>(y2, bn7_g, bn7_b, (float*)d_out, 512);
}

// round 10
// speedup vs baseline: 1.0603x; 1.0603x over previous
#include <cuda_runtime.h>
#include <math.h>

#define B_  32
#define T0_ 2048
#define T1_ 2044
#define T2_ 2040
#define T3_ 2034

// ---------------- scratch (device globals; no allocations allowed) ----------
__device__ float g_xT  [20   * B_ * T0_];
__device__ float g_act1[512  * B_ * T1_];
__device__ float g_act2[512  * B_ * T2_];
__device__ float g_act3[512  * B_ * T3_];
__device__ float g_act4[512  * B_ * T3_];
__device__ float g_act5[1500 * B_ * T3_];
__device__ float g_scl [1500];
__device__ float g_shf [1500];
__device__ float g_wT  [512 * 1536];     // transposed folded weights [K][M]
__device__ float g_bp  [1500];           // folded bias
__device__ float g_pool[B_ * 3000];
__device__ float g_y1  [B_ * 512];
__device__ float g_y2  [B_ * 512];

// ---------------- transpose x[b][t][f] -> xT[f][b][t] -----------------------
__global__ void transpose_x(const float* __restrict__ x, float* __restrict__ xT) {
    int idx = blockIdx.x * blockDim.x + threadIdx.x;
    const int total = B_ * T0_ * 20;
    if (idx >= total) return;
    int f = idx % 20;
    int t = (idx / 20) % T0_;
    int b = idx / (20 * T0_);
    xT[((size_t)f * B_ + b) * T0_ + t] = x[idx];
}

// ---------------- weight prep: transpose + fold BN scale ---------------------
// Wt[k*M + m] = W[m*K + k] * scl[k/C]
__global__ void prep_wT(const float* __restrict__ W, const float* __restrict__ scl,
                        float* __restrict__ Wt, int M, int K, int C, int hasAff)
{
    int idx = blockIdx.x * blockDim.x + threadIdx.x;
    if (idx >= M * K) return;
    int k = idx / M, m = idx - k * M;
    float sA = hasAff ? scl[k / C] : 1.f;
    Wt[idx] = W[(size_t)m * K + k] * sA;
}
// bp[m] = bias[m] + sum_k W[m,k]*shf[k/C]
__global__ void prep_bias(const float* __restrict__ W, const float* __restrict__ bias,
                          const float* __restrict__ shf, float* __restrict__ bp,
                          int M, int K, int C, int hasAff)
{
    int m    = blockIdx.x * (blockDim.x >> 5) + (threadIdx.x >> 5);
    int lane = threadIdx.x & 31;
    if (m >= M) return;
    float acc = 0.f;
    if (hasAff)
        for (int k = lane; k < K; k += 32) acc += W[(size_t)m * K + k] * shf[k / C];
#pragma unroll
    for (int off = 16; off; off >>= 1) acc += __shfl_xor_sync(0xffffffffu, acc, off);
    if (lane == 0) bp[m] = bias[m] + acc;
}

// ---------------- TF32 / cp.async helpers ------------------------------------
__device__ __forceinline__ unsigned f2tf32(float v) {
    unsigned r;
    asm("cvt.rna.tf32.f32 %0, %1;" : "=r"(r) : "f"(v));
    return r;
}
__device__ __forceinline__ void split_tf32(float v, unsigned &hi, unsigned &lo) {
    hi = f2tf32(v);
    lo = f2tf32(v - __uint_as_float(hi));
}
__device__ __forceinline__ void mma_tf32(float c[4],
                                         unsigned a0, unsigned a1, unsigned a2, unsigned a3,
                                         unsigned b0, unsigned b1) {
    asm("mma.sync.aligned.m16n8k8.row.col.f32.tf32.tf32.f32 "
        "{%0,%1,%2,%3}, {%4,%5,%6,%7}, {%8,%9}, {%0,%1,%2,%3};"
        : "+f"(c[0]), "+f"(c[1]), "+f"(c[2]), "+f"(c[3])
        : "r"(a0), "r"(a1), "r"(a2), "r"(a3), "r"(b0), "r"(b1));
}
__device__ __forceinline__ unsigned smem_u32(const void* p) {
    return (unsigned)__cvta_generic_to_shared(p);
}
__device__ __forceinline__ void cp16(unsigned dst, const float* src, int sbytes) {
    asm volatile("cp.async.ca.shared.global [%0], [%1], 16, %2;"
                 :: "r"(dst), "l"(src), "r"(sbytes));
}
__device__ __forceinline__ void cp4(unsigned dst, const float* src, int sbytes) {
    asm volatile("cp.async.ca.shared.global [%0], [%1], 4, %2;"
                 :: "r"(dst), "l"(src), "r"(sbytes));
}

// ---------------- fused splice + 1x1 conv GEMM -------------------------------
// 3xTF32 split-precision tensor-core GEMM; block 128x128x16, 8 warps, warp 64x32.
// Raw fp32 in smem, hi/lo split at fragment load (R8 consumer).
// cp.async double-buffered producer: zero register staging.
#define TBM 128
#define TBN 128
#define TBK 16
#define PAD 8

__global__ __launch_bounds__(256, 2)
void gemm_splice(const float* __restrict__ Wt, const float* __restrict__ bias,
                 const float* __restrict__ X, float* __restrict__ Y,
                 int M, int K, int C, int offStride,
                 int Tin, int Tout, int actMode)
{
    __shared__ float As[2][TBK][TBM + PAD];
    __shared__ float Bs[2][TBK][TBN + PAD];

    const int b     = blockIdx.z;
    const int m0    = blockIdx.y * TBM;
    const int tbase = blockIdx.x * TBN;
    const int tid   = threadIdx.x;

    const int lane  = tid & 31;
    const int warp  = tid >> 5;
    const int g     = lane >> 2;
    const int tg    = lane & 3;
    const int wm    = (warp & 1) * 64;
    const int wn    = (warp >> 1) * 32;

    const float* Xb = X + (size_t)b * Tin;

    float acc[4][4][4];
#pragma unroll
    for (int mi = 0; mi < 4; mi++)
#pragma unroll
        for (int ni = 0; ni < 4; ni++)
#pragma unroll
            for (int r = 0; r < 4; r++) acc[mi][ni][r] = 0.f;

    // producer mapping
    const int aKrow = tid >> 4;          // 0..15
    const int aMcol = (tid & 15) * 8;    // 0..120
    const int bRow  = tid >> 4;          // 0..15
    const int bCol0 = (tid & 15) * 8;

    const int nT = (K + TBK - 1) / TBK;

#define PREFETCH(K0, BUF)                                                          \
    {                                                                              \
        int kA = (K0) + aKrow;                                                     \
        const float* asrc = Wt + (size_t)kA * M + m0 + aMcol;                      \
        int av = (kA < K) ? (M - (m0 + aMcol)) : 0;                                \
        int s0 = min(max(av, 0), 4) * 4;                                           \
        int s1 = min(max(av - 4, 0), 4) * 4;                                       \
        cp16(smem_u32(&As[BUF][aKrow][aMcol]),     asrc,     s0);                  \
        cp16(smem_u32(&As[BUF][aKrow][aMcol + 4]), asrc + 4, s1);                  \
        int kB = (K0) + bRow;                                                      \
        bool kv = (kB < K);                                                        \
        int f = 0, off = 0;                                                        \
        if (kv) { f = kB / C; off = (kB - f * C) * offStride; }                    \
        const float* bsrc = Xb + (size_t)f * (B_ * (size_t)Tin) + off + tbase + bCol0; \
        _Pragma("unroll")                                                          \
        for (int j = 0; j < 8; j++) {                                              \
            int t = tbase + bCol0 + j;                                             \
            cp4(smem_u32(&Bs[BUF][bRow][bCol0 + j]), bsrc + j,                     \
                (kv && t < Tout) ? 4 : 0);                                         \
        }                                                                          \
        asm volatile("cp.async.commit_group;");                                    \
    }

    PREFETCH(0, 0);
    asm volatile("cp.async.wait_group 0;");
    __syncthreads();

    for (int it = 0; it < nT; it++) {
        const int buf = it & 1;
        if (it + 1 < nT) PREFETCH((it + 1) * TBK, buf ^ 1);

#pragma unroll
        for (int kk = 0; kk < TBK; kk += 8) {
            unsigned afh[4][4], afl[4][4], bfh[4][2], bfl[4][2];
#pragma unroll
            for (int mi = 0; mi < 4; mi++) {
                int m = wm + mi * 16 + g;
                float r0 = As[buf][kk + tg    ][m];
                float r1 = As[buf][kk + tg    ][m + 8];
                float r2 = As[buf][kk + tg + 4][m];
                float r3 = As[buf][kk + tg + 4][m + 8];
                split_tf32(r0, afh[mi][0], afl[mi][0]);
                split_tf32(r1, afh[mi][1], afl[mi][1]);
                split_tf32(r2, afh[mi][2], afl[mi][2]);
                split_tf32(r3, afh[mi][3], afl[mi][3]);
            }
#pragma unroll
            for (int ni = 0; ni < 4; ni++) {
                int n = wn + ni * 8 + g;
                float r0 = Bs[buf][kk + tg    ][n];
                float r1 = Bs[buf][kk + tg + 4][n];
                split_tf32(r0, bfh[ni][0], bfl[ni][0]);
                split_tf32(r1, bfh[ni][1], bfl[ni][1]);
            }
#pragma unroll
            for (int mi = 0; mi < 4; mi++)
#pragma unroll
                for (int ni = 0; ni < 4; ni++) {
                    mma_tf32(acc[mi][ni], afh[mi][0], afh[mi][1], afh[mi][2], afh[mi][3],
                             bfh[ni][0], bfh[ni][1]);
                    mma_tf32(acc[mi][ni], afh[mi][0], afh[mi][1], afh[mi][2], afh[mi][3],
                             bfl[ni][0], bfl[ni][1]);
                    mma_tf32(acc[mi][ni], afl[mi][0], afl[mi][1], afl[mi][2], afl[mi][3],
                             bfh[ni][0], bfh[ni][1]);
                }
        }

        if (it + 1 < nT) asm volatile("cp.async.wait_group 0;");
        __syncthreads();
    }

    // ---- epilogue: bias + activation, write [M][B][Tout] ----
    const size_t strideY = (size_t)B_ * Tout;
#pragma unroll
    for (int mi = 0; mi < 4; mi++) {
        int mA = m0 + wm + mi * 16 + g;
        int mB = mA + 8;
        float biA = (mA < M) ? bias[mA] : 0.f;
        float biB = (mB < M) ? bias[mB] : 0.f;
#pragma unroll
        for (int ni = 0; ni < 4; ni++) {
            int t = tbase + wn + ni * 8 + tg * 2;
            if (t >= Tout) continue;
            if (mA < M) {
                float2 v;
                v.x = fmaxf(acc[mi][ni][0] + biA, 0.f);
                v.y = fmaxf(acc[mi][ni][1] + biA, 0.f);
                if (actMode) { v.x = fminf(v.x, 6.f); v.y = fminf(v.y, 6.f); }
                *(float2*)&Y[(size_t)mA * strideY + (size_t)b * Tout + t] = v;
            }
            if (mB < M) {
                float2 v;
                v.x = fmaxf(acc[mi][ni][2] + biB, 0.f);
                v.y = fmaxf(acc[mi][ni][3] + biB, 0.f);
                if (actMode) { v.x = fminf(v.x, 6.f); v.y = fminf(v.y, 6.f); }
                *(float2*)&Y[(size_t)mB * strideY + (size_t)b * Tout + t] = v;
            }
        }
    }
#undef PREFETCH
}

// ---------------- per-channel batch-norm stats (over B*T) -------------------
__global__ void channel_stats(const float* __restrict__ Y, int N,
                              const float* __restrict__ gam, const float* __restrict__ bet,
                              float* __restrict__ scl, float* __restrict__ shf)
{
    int c = blockIdx.x;
    const float4* p = (const float4*)(Y + (size_t)c * N);
    int n4 = N >> 2;
    float s1 = 0.f, s2 = 0.f;
    for (int i = threadIdx.x; i < n4; i += blockDim.x) {
        float4 v = p[i];
        s1 += v.x + v.y + v.z + v.w;
        s2 += v.x*v.x + v.y*v.y + v.z*v.z + v.w*v.w;
    }
    __shared__ float r1[256], r2[256];
    r1[threadIdx.x] = s1; r2[threadIdx.x] = s2;
    __syncthreads();
    for (int s = 128; s > 0; s >>= 1) {
        if (threadIdx.x < s) {
            r1[threadIdx.x] += r1[threadIdx.x + s];
            r2[threadIdx.x] += r2[threadIdx.x + s];
        }
        __syncthreads();
    }
    if (threadIdx.x == 0) {
        float m   = r1[0] / (float)N;
        float var = r2[0] / (float)N - m * m;
        float inv = rsqrtf(var + 1e-5f);
        float g   = gam ? gam[c] : 1.f;
        float be  = bet ? bet[c] : 0.f;
        float A   = g * inv;
        scl[c] = A;
        shf[c] = be - m * A;
    }
}

// ---------------- fused bn5 stats + pooled mean/std --------------------------
__global__ void stats_pool(const float* __restrict__ A,
                           const float* __restrict__ gam, const float* __restrict__ bet,
                           float* __restrict__ P)
{
    int c   = blockIdx.x;
    int tid = threadIdx.x;
    int bb  = tid >> 3;
    int sub = tid & 7;
    const float* p = A + ((size_t)c * B_ + bb) * T3_;
    float s1 = 0.f, s2 = 0.f;
    const int n2 = T3_ >> 1;
    for (int i = sub; i < n2; i += 8) {
        float2 v = *(const float2*)(p + 2 * i);
        s1 += v.x + v.y;
        s2 += v.x * v.x + v.y * v.y;
    }
    __shared__ float r1[256], r2[256];
    r1[tid] = s1; r2[tid] = s2;
    __syncthreads();
    if (sub < 4) { r1[tid] += r1[tid + 4]; r2[tid] += r2[tid + 4]; }
    __syncthreads();
    if (sub < 2) { r1[tid] += r1[tid + 2]; r2[tid] += r2[tid + 2]; }
    __syncthreads();
    if (sub == 0) { r1[tid] += r1[tid + 1]; r2[tid] += r2[tid + 1]; }
    __syncthreads();
    __shared__ float shA, shD;
    if (tid == 0) {
        float t1 = 0.f, t2 = 0.f;
        for (int i = 0; i < 32; i++) { t1 += r1[i * 8]; t2 += r2[i * 8]; }
        float m   = t1 / (float)(B_ * T3_);
        float var = t2 / (float)(B_ * T3_) - m * m;
        float inv = rsqrtf(var + 1e-5f);
        float Aa  = gam[c] * inv;
        shA = Aa;
        shD = bet[c] - m * Aa;
    }
    __syncthreads();
    if (sub == 0) {
        float m   = r1[tid] / (float)T3_;
        float var = (r2[tid] - (float)T3_ * m * m) / (float)(T3_ - 1);
        P[bb * 3000 + c]        = shA * m + shD;
        P[bb * 3000 + 1500 + c] = fabsf(shA) * sqrtf(fmaxf(var, 0.f));
    }
}

// ---------------- dense + relu6 (one warp per output) -----------------------
__global__ void dense_relu6(const float* __restrict__ W, const float* __restrict__ bias,
                            const float* __restrict__ X, float* __restrict__ Y,
                            int M, int K)
{
    int gw   = (blockIdx.x * blockDim.x + threadIdx.x) >> 5;
    int lane = threadIdx.x & 31;
    if (gw >= B_ * M) return;
    int b = gw / M, o = gw - b * M;
    const float* w = W + (size_t)o * K;
    const float* x = X + (size_t)b * K;
    float s = 0.f;
    for (int k = lane; k < K; k += 32) s += w[k] * x[k];
#pragma unroll
    for (int off = 16; off; off >>= 1) s += __shfl_xor_sync(0xffffffffu, s, off);
    if (lane == 0) {
        float v = s + bias[o];
        Y[(size_t)b * M + o] = fminf(fmaxf(v, 0.f), 6.f);
    }
}

// ---------------- batch-norm over batch dim (B=32 == warp) ------------------
__global__ void bn_batch(const float* __restrict__ Y, const float* __restrict__ gam,
                         const float* __restrict__ bet, float* __restrict__ Out, int M)
{
    int o    = (blockIdx.x * blockDim.x + threadIdx.x) >> 5;
    int lane = threadIdx.x & 31;
    if (o >= M) return;
    float v  = Y[(size_t)lane * M + o];
    float s1 = v, s2 = v * v;
#pragma unroll
    for (int off = 16; off; off >>= 1) {
        s1 += __shfl_xor_sync(0xffffffffu, s1, off);
        s2 += __shfl_xor_sync(0xffffffffu, s2, off);
    }
    float m   = s1 * (1.f / 32.f);
    float var = s2 * (1.f / 32.f) - m * m;
    float r   = rsqrtf(var + 1e-5f);
    Out[(size_t)lane * M + o] = (v - m) * r * gam[o] + bet[o];
}

// ---------------- launch ----------------------------------------------------
extern "C" void kernel_launch(void* const* d_in, const int* in_sizes, int n_in,
                              void* d_out, int out_size)
{
    const float* x     = (const float*)d_in[0];
    const float* h1_w  = (const float*)d_in[1];
    const float* h1_b  = (const float*)d_in[2];
    const float* h2_w  = (const float*)d_in[3];
    const float* h2_b  = (const float*)d_in[4];
    const float* bn2_g = (const float*)d_in[5];
    const float* bn2_b = (const float*)d_in[6];
    const float* h3_w  = (const float*)d_in[7];
    const float* h3_b  = (const float*)d_in[8];
    const float* bn3_g = (const float*)d_in[9];
    const float* bn3_b = (const float*)d_in[10];
    const float* h4_w  = (const float*)d_in[11];
    const float* h4_b  = (const float*)d_in[12];
    const float* bn4_g = (const float*)d_in[13];
    const float* bn4_b = (const float*)d_in[14];
    const float* h5_w  = (const float*)d_in[15];
    const float* h5_b  = (const float*)d_in[16];
    const float* bn5_g = (const float*)d_in[17];
    const float* bn5_b = (const float*)d_in[18];
    const float* l1_w  = (const float*)d_in[19];
    const float* l1_b  = (const float*)d_in[20];
    const float* bn6_g = (const float*)d_in[21];
    const float* bn6_b = (const float*)d_in[22];
    const float* l2_w  = (const float*)d_in[23];
    const float* l2_b  = (const float*)d_in[24];
    const float* bn7_g = (const float*)d_in[25];
    const float* bn7_b = (const float*)d_in[26];

    float *xT, *a1, *a2, *a3, *a4, *a5, *scl, *shf, *wT, *bp, *pool, *y1, *y2;
    cudaGetSymbolAddress((void**)&xT,   g_xT);
    cudaGetSymbolAddress((void**)&a1,   g_act1);
    cudaGetSymbolAddress((void**)&a2,   g_act2);
    cudaGetSymbolAddress((void**)&a3,   g_act3);
    cudaGetSymbolAddress((void**)&a4,   g_act4);
    cudaGetSymbolAddress((void**)&a5,   g_act5);
    cudaGetSymbolAddress((void**)&scl,  g_scl);
    cudaGetSymbolAddress((void**)&shf,  g_shf);
    cudaGetSymbolAddress((void**)&wT,   g_wT);
    cudaGetSymbolAddress((void**)&bp,   g_bp);
    cudaGetSymbolAddress((void**)&pool, g_pool);
    cudaGetSymbolAddress((void**)&y1,   g_y1);
    cudaGetSymbolAddress((void**)&y2,   g_y2);

    const int N1 = B_ * T1_;
    const int N2 = B_ * T2_;
    const int N3 = B_ * T3_;

    transpose_x<<<(B_ * T0_ * 20 + 255) / 256, 256>>>(x, xT);

    // Layer 1
    prep_wT<<<(512 * 100 + 255) / 256, 256>>>(h1_w, nullptr, wT, 512, 100, 5, 0);
    prep_bias<<<(512 + 7) / 8, 256>>>(h1_w, h1_b, nullptr, bp, 512, 100, 5, 0);
    gemm_splice<<<dim3((T1_ + 127) / 128, 4, B_), 256>>>(
        wT, bp, xT, a1, 512, 100, 5, 1, T0_, T1_, 0);
    channel_stats<<<512, 256>>>(a1, N1, nullptr, nullptr, scl, shf);

    // Layer 2
    prep_wT<<<(512 * 1536 + 255) / 256, 256>>>(h2_w, scl, wT, 512, 1536, 3, 1);
    prep_bias<<<(512 + 7) / 8, 256>>>(h2_w, h2_b, shf, bp, 512, 1536, 3, 1);
    gemm_splice<<<dim3((T2_ + 127) / 128, 4, B_), 256>>>(
        wT, bp, a1, a2, 512, 1536, 3, 2, T1_, T2_, 0);
    channel_stats<<<512, 256>>>(a2, N2, bn2_g, bn2_b, scl, shf);

    // Layer 3
    prep_wT<<<(512 * 1536 + 255) / 256, 256>>>(h3_w, scl, wT, 512, 1536, 3, 1);
    prep_bias<<<(512 + 7) / 8, 256>>>(h3_w, h3_b, shf, bp, 512, 1536, 3, 1);
    gemm_splice<<<dim3((T3_ + 127) / 128, 4, B_), 256>>>(
        wT, bp, a2, a3, 512, 1536, 3, 3, T2_, T3_, 0);
    channel_stats<<<512, 256>>>(a3, N3, bn3_g, bn3_b, scl, shf);

    // Layer 4
    prep_wT<<<(512 * 512 + 255) / 256, 256>>>(h4_w, scl, wT, 512, 512, 1, 1);
    prep_bias<<<(512 + 7) / 8, 256>>>(h4_w, h4_b, shf, bp, 512, 512, 1, 1);
    gemm_splice<<<dim3((T3_ + 127) / 128, 4, B_), 256>>>(
        wT, bp, a3, a4, 512, 512, 1, 0, T3_, T3_, 1);
    channel_stats<<<512, 256>>>(a4, N3, bn4_g, bn4_b, scl, shf);

    // Layer 5
    prep_wT<<<(1500 * 512 + 255) / 256, 256>>>(h5_w, scl, wT, 1500, 512, 1, 1);
    prep_bias<<<(1500 + 7) / 8, 256>>>(h5_w, h5_b, shf, bp, 1500, 512, 1, 1);
    gemm_splice<<<dim3((T3_ + 127) / 128, 12, B_), 256>>>(
        wT, bp, a4, a5, 1500, 512, 1, 0, T3_, T3_, 1);

    stats_pool<<<1500, 256>>>(a5, bn5_g, bn5_b, pool);

    dense_relu6<<<(B_ * 512 * 32 + 255) / 256, 256>>>(l1_w, l1_b, pool, y1, 512, 3000);
    bn_batch<<<(512 * 32 + 255) / 256, 256>>>(y1, bn6_g, bn6_b, y1, 512);

    dense_relu6<<<(B_ * 512 * 32 + 255) / 256, 256>>>(l2_w, l2_b, y1, y2, 512, 512);
    bn_batch<<<(512 * 32 + 255) / 256, 256>>>(y2, bn7_g, bn7_b, (float*)d_out, 512);
}

// round 11
// speedup vs baseline: 1.6150x; 1.5232x over previous
#include <cuda_runtime.h>
#include <math.h>

#define B_  32
#define T0_ 2048
#define T1_ 2044
#define T2_ 2040
#define T3_ 2034

// ---------------- scratch (device globals; no allocations allowed) ----------
__device__ float g_xT  [20   * B_ * T0_];
__device__ float g_act1[512  * B_ * T1_];
__device__ float g_act2[512  * B_ * T2_];
__device__ float g_act3[512  * B_ * T3_];
__device__ float g_act4[512  * B_ * T3_];
__device__ float g_act5[1500 * B_ * T3_];
__device__ float g_scl [1500];
__device__ float g_shf [1500];
__device__ float g_wT  [512 * 1536];     // transposed folded weights [K][M]
__device__ float g_bp  [1500];           // folded bias
__device__ float g_pool[B_ * 3000];
__device__ float g_y1  [B_ * 512];
__device__ float g_y2  [B_ * 512];

// ---------------- transpose x[b][t][f] -> xT[f][b][t] -----------------------
__global__ void transpose_x(const float* __restrict__ x, float* __restrict__ xT) {
    int idx = blockIdx.x * blockDim.x + threadIdx.x;
    const int total = B_ * T0_ * 20;
    if (idx >= total) return;
    int f = idx % 20;
    int t = (idx / 20) % T0_;
    int b = idx / (20 * T0_);
    xT[((size_t)f * B_ + b) * T0_ + t] = x[idx];
}

// ---------------- weight prep: transpose + fold BN scale ---------------------
__global__ void prep_wT(const float* __restrict__ W, const float* __restrict__ scl,
                        float* __restrict__ Wt, int M, int K, int C, int hasAff)
{
    int idx = blockIdx.x * blockDim.x + threadIdx.x;
    if (idx >= M * K) return;
    int k = idx / M, m = idx - k * M;
    float sA = hasAff ? scl[k / C] : 1.f;
    Wt[idx] = W[(size_t)m * K + k] * sA;
}
__global__ void prep_bias(const float* __restrict__ W, const float* __restrict__ bias,
                          const float* __restrict__ shf, float* __restrict__ bp,
                          int M, int K, int C, int hasAff)
{
    int m    = blockIdx.x * (blockDim.x >> 5) + (threadIdx.x >> 5);
    int lane = threadIdx.x & 31;
    if (m >= M) return;
    float acc = 0.f;
    if (hasAff)
        for (int k = lane; k < K; k += 32) acc += W[(size_t)m * K + k] * shf[k / C];
#pragma unroll
    for (int off = 16; off; off >>= 1) acc += __shfl_xor_sync(0xffffffffu, acc, off);
    if (lane == 0) bp[m] = bias[m] + acc;
}

// ---------------- BF16 split / mma helpers -----------------------------------
// Pack two fp32 into bf16x2 hi, and the exact residuals into bf16x2 lo.
__device__ __forceinline__ void pack_split_bf16(float v0, float v1,
                                                unsigned &hi, unsigned &lo) {
    unsigned h;
    asm("cvt.rn.bf16x2.f32 %0, %1, %2;" : "=r"(h) : "f"(v1), "f"(v0));
    float h0 = __uint_as_float(h << 16);
    float h1 = __uint_as_float(h & 0xffff0000u);
    float l0 = v0 - h0;
    float l1 = v1 - h1;
    unsigned l;
    asm("cvt.rn.bf16x2.f32 %0, %1, %2;" : "=r"(l) : "f"(l1), "f"(l0));
    hi = h; lo = l;
}

__device__ __forceinline__ void mma_bf16(float c[4],
                                         unsigned a0, unsigned a1, unsigned a2, unsigned a3,
                                         unsigned b0, unsigned b1) {
    asm("mma.sync.aligned.m16n8k16.row.col.f32.bf16.bf16.f32 "
        "{%0,%1,%2,%3}, {%4,%5,%6,%7}, {%8,%9}, {%0,%1,%2,%3};"
        : "+f"(c[0]), "+f"(c[1]), "+f"(c[2]), "+f"(c[3])
        : "r"(a0), "r"(a1), "r"(a2), "r"(a3), "r"(b0), "r"(b1));
}

__device__ __forceinline__ unsigned smem_u32(const void* p) {
    return (unsigned)__cvta_generic_to_shared(p);
}
__device__ __forceinline__ void cp16(unsigned dst, const float* src, int sbytes) {
    asm volatile("cp.async.ca.shared.global [%0], [%1], 16, %2;"
                 :: "r"(dst), "l"(src), "r"(sbytes));
}
__device__ __forceinline__ void cp4(unsigned dst, const float* src, int sbytes) {
    asm volatile("cp.async.ca.shared.global [%0], [%1], 4, %2;"
                 :: "r"(dst), "l"(src), "r"(sbytes));
}

// ---------------- fused splice + 1x1 conv GEMM -------------------------------
// 3xBF16 split-precision tensor-core GEMM (m16n8k16, fp32 accumulate).
// Block 128x128x16, 8 warps, warp tile 64x32. Raw fp32 in smem; split+pack at
// fragment load. Pitch 132 (pad 4): bank(row 2tg, col g) = 8*tg+g, conflict-free.
// cp.async double-buffered producer (zero register staging, zero-fill tails).
#define TBM 128
#define TBN 128
#define TBK 16
#define PAD 4

__global__ __launch_bounds__(256, 2)
void gemm_splice(const float* __restrict__ Wt, const float* __restrict__ bias,
                 const float* __restrict__ X, float* __restrict__ Y,
                 int M, int K, int C, int offStride,
                 int Tin, int Tout, int actMode)
{
    __shared__ float As[2][TBK][TBM + PAD];
    __shared__ float Bs[2][TBK][TBN + PAD];

    const int b     = blockIdx.z;
    const int m0    = blockIdx.y * TBM;
    const int tbase = blockIdx.x * TBN;
    const int tid   = threadIdx.x;

    const int lane  = tid & 31;
    const int warp  = tid >> 5;
    const int g     = lane >> 2;
    const int tg    = lane & 3;
    const int wm    = (warp & 1) * 64;
    const int wn    = (warp >> 1) * 32;

    const float* Xb = X + (size_t)b * Tin;

    float acc[4][4][4];
#pragma unroll
    for (int mi = 0; mi < 4; mi++)
#pragma unroll
        for (int ni = 0; ni < 4; ni++)
#pragma unroll
            for (int r = 0; r < 4; r++) acc[mi][ni][r] = 0.f;

    const int aKrow = tid >> 4;
    const int aMcol = (tid & 15) * 8;
    const int bRow  = tid >> 4;
    const int bCol0 = (tid & 15) * 8;

    const int nT = (K + TBK - 1) / TBK;

#define PREFETCH(K0, BUF)                                                          \
    {                                                                              \
        int kA = (K0) + aKrow;                                                     \
        const float* asrc = Wt + (size_t)kA * M + m0 + aMcol;                      \
        int av = (kA < K) ? (M - (m0 + aMcol)) : 0;                                \
        int s0 = min(max(av, 0), 4) * 4;                                           \
        int s1 = min(max(av - 4, 0), 4) * 4;                                       \
        cp16(smem_u32(&As[BUF][aKrow][aMcol]),     asrc,     s0);                  \
        cp16(smem_u32(&As[BUF][aKrow][aMcol + 4]), asrc + 4, s1);                  \
        int kB = (K0) + bRow;                                                      \
        bool kv = (kB < K);                                                        \
        int f = 0, off = 0;                                                        \
        if (kv) { f = kB / C; off = (kB - f * C) * offStride; }                    \
        const float* bsrc = Xb + (size_t)f * (B_ * (size_t)Tin) + off + tbase + bCol0; \
        _Pragma("unroll")                                                          \
        for (int j = 0; j < 8; j++) {                                              \
            int t = tbase + bCol0 + j;                                             \
            cp4(smem_u32(&Bs[BUF][bRow][bCol0 + j]), bsrc + j,                     \
                (kv && t < Tout) ? 4 : 0);                                         \
        }                                                                          \
        asm volatile("cp.async.commit_group;");                                    \
    }

    PREFETCH(0, 0);
    asm volatile("cp.async.wait_group 0;");
    __syncthreads();

    for (int it = 0; it < nT; it++) {
        const int buf = it & 1;
        if (it + 1 < nT) PREFETCH((it + 1) * TBK, buf ^ 1);

        // ---- one m16n8k16 step covers the whole 16-deep tile ----
        unsigned afh[4][4], afl[4][4], bfh[4][2], bfl[4][2];
#pragma unroll
        for (int mi = 0; mi < 4; mi++) {
            int m = wm + mi * 16 + g;
            pack_split_bf16(As[buf][2*tg    ][m    ], As[buf][2*tg + 1][m    ],
                            afh[mi][0], afl[mi][0]);
            pack_split_bf16(As[buf][2*tg    ][m + 8], As[buf][2*tg + 1][m + 8],
                            afh[mi][1], afl[mi][1]);
            pack_split_bf16(As[buf][2*tg + 8][m    ], As[buf][2*tg + 9][m    ],
                            afh[mi][2], afl[mi][2]);
            pack_split_bf16(As[buf][2*tg + 8][m + 8], As[buf][2*tg + 9][m + 8],
                            afh[mi][3], afl[mi][3]);
        }
#pragma unroll
        for (int ni = 0; ni < 4; ni++) {
            int n = wn + ni * 8 + g;
            pack_split_bf16(Bs[buf][2*tg    ][n], Bs[buf][2*tg + 1][n],
                            bfh[ni][0], bfl[ni][0]);
            pack_split_bf16(Bs[buf][2*tg + 8][n], Bs[buf][2*tg + 9][n],
                            bfh[ni][1], bfl[ni][1]);
        }
#pragma unroll
        for (int mi = 0; mi < 4; mi++)
#pragma unroll
            for (int ni = 0; ni < 4; ni++) {
                mma_bf16(acc[mi][ni], afh[mi][0], afh[mi][1], afh[mi][2], afh[mi][3],
                         bfh[ni][0], bfh[ni][1]);
                mma_bf16(acc[mi][ni], afh[mi][0], afh[mi][1], afh[mi][2], afh[mi][3],
                         bfl[ni][0], bfl[ni][1]);
                mma_bf16(acc[mi][ni], afl[mi][0], afl[mi][1], afl[mi][2], afl[mi][3],
                         bfh[ni][0], bfh[ni][1]);
            }

        if (it + 1 < nT) asm volatile("cp.async.wait_group 0;");
        __syncthreads();
    }

    // ---- epilogue: bias + activation, write [M][B][Tout] ----
    const size_t strideY = (size_t)B_ * Tout;
#pragma unroll
    for (int mi = 0; mi < 4; mi++) {
        int mA = m0 + wm + mi * 16 + g;
        int mB = mA + 8;
        float biA = (mA < M) ? bias[mA] : 0.f;
        float biB = (mB < M) ? bias[mB] : 0.f;
#pragma unroll
        for (int ni = 0; ni < 4; ni++) {
            int t = tbase + wn + ni * 8 + tg * 2;
            if (t >= Tout) continue;
            if (mA < M) {
                float2 v;
                v.x = fmaxf(acc[mi][ni][0] + biA, 0.f);
                v.y = fmaxf(acc[mi][ni][1] + biA, 0.f);
                if (actMode) { v.x = fminf(v.x, 6.f); v.y = fminf(v.y, 6.f); }
                *(float2*)&Y[(size_t)mA * strideY + (size_t)b * Tout + t] = v;
            }
            if (mB < M) {
                float2 v;
                v.x = fmaxf(acc[mi][ni][2] + biB, 0.f);
                v.y = fmaxf(acc[mi][ni][3] + biB, 0.f);
                if (actMode) { v.x = fminf(v.x, 6.f); v.y = fminf(v.y, 6.f); }
                *(float2*)&Y[(size_t)mB * strideY + (size_t)b * Tout + t] = v;
            }
        }
    }
#undef PREFETCH
}

// ---------------- per-channel batch-norm stats (over B*T) -------------------
__global__ void channel_stats(const float* __restrict__ Y, int N,
                              const float* __restrict__ gam, const float* __restrict__ bet,
                              float* __restrict__ scl, float* __restrict__ shf)
{
    int c = blockIdx.x;
    const float4* p = (const float4*)(Y + (size_t)c * N);
    int n4 = N >> 2;
    float s1 = 0.f, s2 = 0.f;
    for (int i = threadIdx.x; i < n4; i += blockDim.x) {
        float4 v = p[i];
        s1 += v.x + v.y + v.z + v.w;
        s2 += v.x*v.x + v.y*v.y + v.z*v.z + v.w*v.w;
    }
    __shared__ float r1[256], r2[256];
    r1[threadIdx.x] = s1; r2[threadIdx.x] = s2;
    __syncthreads();
    for (int s = 128; s > 0; s >>= 1) {
        if (threadIdx.x < s) {
            r1[threadIdx.x] += r1[threadIdx.x + s];
            r2[threadIdx.x] += r2[threadIdx.x + s];
        }
        __syncthreads();
    }
    if (threadIdx.x == 0) {
        float m   = r1[0] / (float)N;
        float var = r2[0] / (float)N - m * m;
        float inv = rsqrtf(var + 1e-5f);
        float g   = gam ? gam[c] : 1.f;
        float be  = bet ? bet[c] : 0.f;
        float A   = g * inv;
        scl[c] = A;
        shf[c] = be - m * A;
    }
}

// ---------------- fused bn5 stats + pooled mean/std --------------------------
__global__ void stats_pool(const float* __restrict__ A,
                           const float* __restrict__ gam, const float* __restrict__ bet,
                           float* __restrict__ P)
{
    int c   = blockIdx.x;
    int tid = threadIdx.x;
    int bb  = tid >> 3;
    int sub = tid & 7;
    const float* p = A + ((size_t)c * B_ + bb) * T3_;
    float s1 = 0.f, s2 = 0.f;
    const int n2 = T3_ >> 1;
    for (int i = sub; i < n2; i += 8) {
        float2 v = *(const float2*)(p + 2 * i);
        s1 += v.x + v.y;
        s2 += v.x * v.x + v.y * v.y;
    }
    __shared__ float r1[256], r2[256];
    r1[tid] = s1; r2[tid] = s2;
    __syncthreads();
    if (sub < 4) { r1[tid] += r1[tid + 4]; r2[tid] += r2[tid + 4]; }
    __syncthreads();
    if (sub < 2) { r1[tid] += r1[tid + 2]; r2[tid] += r2[tid + 2]; }
    __syncthreads();
    if (sub == 0) { r1[tid] += r1[tid + 1]; r2[tid] += r2[tid + 1]; }
    __syncthreads();
    __shared__ float shA, shD;
    if (tid == 0) {
        float t1 = 0.f, t2 = 0.f;
        for (int i = 0; i < 32; i++) { t1 += r1[i * 8]; t2 += r2[i * 8]; }
        float m   = t1 / (float)(B_ * T3_);
        float var = t2 / (float)(B_ * T3_) - m * m;
        float inv = rsqrtf(var + 1e-5f);
        float Aa  = gam[c] * inv;
        shA = Aa;
        shD = bet[c] - m * Aa;
    }
    __syncthreads();
    if (sub == 0) {
        float m   = r1[tid] / (float)T3_;
        float var = (r2[tid] - (float)T3_ * m * m) / (float)(T3_ - 1);
        P[bb * 3000 + c]        = shA * m + shD;
        P[bb * 3000 + 1500 + c] = fabsf(shA) * sqrtf(fmaxf(var, 0.f));
    }
}

// ---------------- dense + relu6 (one warp per output) -----------------------
__global__ void dense_relu6(const float* __restrict__ W, const float* __restrict__ bias,
                            const float* __restrict__ X, float* __restrict__ Y,
                            int M, int K)
{
    int gw   = (blockIdx.x * blockDim.x + threadIdx.x) >> 5;
    int lane = threadIdx.x & 31;
    if (gw >= B_ * M) return;
    int b = gw / M, o = gw - b * M;
    const float* w = W + (size_t)o * K;
    const float* x = X + (size_t)b * K;
    float s = 0.f;
    for (int k = lane; k < K; k += 32) s += w[k] * x[k];
#pragma unroll
    for (int off = 16; off; off >>= 1) s += __shfl_xor_sync(0xffffffffu, s, off);
    if (lane == 0) {
        float v = s + bias[o];
        Y[(size_t)b * M + o] = fminf(fmaxf(v, 0.f), 6.f);
    }
}

// ---------------- batch-norm over batch dim (B=32 == warp) ------------------
__global__ void bn_batch(const float* __restrict__ Y, const float* __restrict__ gam,
                         const float* __restrict__ bet, float* __restrict__ Out, int M)
{
    int o    = (blockIdx.x * blockDim.x + threadIdx.x) >> 5;
    int lane = threadIdx.x & 31;
    if (o >= M) return;
    float v  = Y[(size_t)lane * M + o];
    float s1 = v, s2 = v * v;
#pragma unroll
    for (int off = 16; off; off >>= 1) {
        s1 += __shfl_xor_sync(0xffffffffu, s1, off);
        s2 += __shfl_xor_sync(0xffffffffu, s2, off);
    }
    float m   = s1 * (1.f / 32.f);
    float var = s2 * (1.f / 32.f) - m * m;
    float r   = rsqrtf(var + 1e-5f);
    Out[(size_t)lane * M + o] = (v - m) * r * gam[o] + bet[o];
}

// ---------------- launch ----------------------------------------------------
extern "C" void kernel_launch(void* const* d_in, const int* in_sizes, int n_in,
                              void* d_out, int out_size)
{
    const float* x     = (const float*)d_in[0];
    const float* h1_w  = (const float*)d_in[1];
    const float* h1_b  = (const float*)d_in[2];
    const float* h2_w  = (const float*)d_in[3];
    const float* h2_b  = (const float*)d_in[4];
    const float* bn2_g = (const float*)d_in[5];
    const float* bn2_b = (const float*)d_in[6];
    const float* h3_w  = (const float*)d_in[7];
    const float* h3_b  = (const float*)d_in[8];
    const float* bn3_g = (const float*)d_in[9];
    const float* bn3_b = (const float*)d_in[10];
    const float* h4_w  = (const float*)d_in[11];
    const float* h4_b  = (const float*)d_in[12];
    const float* bn4_g = (const float*)d_in[13];
    const float* bn4_b = (const float*)d_in[14];
    const float* h5_w  = (const float*)d_in[15];
    const float* h5_b  = (const float*)d_in[16];
    const float* bn5_g = (const float*)d_in[17];
    const float* bn5_b = (const float*)d_in[18];
    const float* l1_w  = (const float*)d_in[19];
    const float* l1_b  = (const float*)d_in[20];
    const float* bn6_g = (const float*)d_in[21];
    const float* bn6_b = (const float*)d_in[22];
    const float* l2_w  = (const float*)d_in[23];
    const float* l2_b  = (const float*)d_in[24];
    const float* bn7_g = (const float*)d_in[25];
    const float* bn7_b = (const float*)d_in[26];

    float *xT, *a1, *a2, *a3, *a4, *a5, *scl, *shf, *wT, *bp, *pool, *y1, *y2;
    cudaGetSymbolAddress((void**)&xT,   g_xT);
    cudaGetSymbolAddress((void**)&a1,   g_act1);
    cudaGetSymbolAddress((void**)&a2,   g_act2);
    cudaGetSymbolAddress((void**)&a3,   g_act3);
    cudaGetSymbolAddress((void**)&a4,   g_act4);
    cudaGetSymbolAddress((void**)&a5,   g_act5);
    cudaGetSymbolAddress((void**)&scl,  g_scl);
    cudaGetSymbolAddress((void**)&shf,  g_shf);
    cudaGetSymbolAddress((void**)&wT,   g_wT);
    cudaGetSymbolAddress((void**)&bp,   g_bp);
    cudaGetSymbolAddress((void**)&pool, g_pool);
    cudaGetSymbolAddress((void**)&y1,   g_y1);
    cudaGetSymbolAddress((void**)&y2,   g_y2);

    const int N1 = B_ * T1_;
    const int N2 = B_ * T2_;
    const int N3 = B_ * T3_;

    transpose_x<<<(B_ * T0_ * 20 + 255) / 256, 256>>>(x, xT);

    // Layer 1
    prep_wT<<<(512 * 100 + 255) / 256, 256>>>(h1_w, nullptr, wT, 512, 100, 5, 0);
    prep_bias<<<(512 + 7) / 8, 256>>>(h1_w, h1_b, nullptr, bp, 512, 100, 5, 0);
    gemm_splice<<<dim3((T1_ + 127) / 128, 4, B_), 256>>>(
        wT, bp, xT, a1, 512, 100, 5, 1, T0_, T1_, 0);
    channel_stats<<<512, 256>>>(a1, N1, nullptr, nullptr, scl, shf);

    // Layer 2
    prep_wT<<<(512 * 1536 + 255) / 256, 256>>>(h2_w, scl, wT, 512, 1536, 3, 1);
    prep_bias<<<(512 + 7) / 8, 256>>>(h2_w, h2_b, shf, bp, 512, 1536, 3, 1);
    gemm_splice<<<dim3((T2_ + 127) / 128, 4, B_), 256>>>(
        wT, bp, a1, a2, 512, 1536, 3, 2, T1_, T2_, 0);
    channel_stats<<<512, 256>>>(a2, N2, bn2_g, bn2_b, scl, shf);

    // Layer 3
    prep_wT<<<(512 * 1536 + 255) / 256, 256>>>(h3_w, scl, wT, 512, 1536, 3, 1);
    prep_bias<<<(512 + 7) / 8, 256>>>(h3_w, h3_b, shf, bp, 512, 1536, 3, 1);
    gemm_splice<<<dim3((T3_ + 127) / 128, 4, B_), 256>>>(
        wT, bp, a2, a3, 512, 1536, 3, 3, T2_, T3_, 0);
    channel_stats<<<512, 256>>>(a3, N3, bn3_g, bn3_b, scl, shf);

    // Layer 4
    prep_wT<<<(512 * 512 + 255) / 256, 256>>>(h4_w, scl, wT, 512, 512, 1, 1);
    prep_bias<<<(512 + 7) / 8, 256>>>(h4_w, h4_b, shf, bp, 512, 512, 1, 1);
    gemm_splice<<<dim3((T3_ + 127) / 128, 4, B_), 256>>>(
        wT, bp, a3, a4, 512, 512, 1, 0, T3_, T3_, 1);
    channel_stats<<<512, 256>>>(a4, N3, bn4_g, bn4_b, scl, shf);

    // Layer 5
    prep_wT<<<(1500 * 512 + 255) / 256, 256>>>(h5_w, scl, wT, 1500, 512, 1, 1);
    prep_bias<<<(1500 + 7) / 8, 256>>>(h5_w, h5_b, shf, bp, 1500, 512, 1, 1);
    gemm_splice<<<dim3((T3_ + 127) / 128, 12, B_), 256>>>(
        wT, bp, a4, a5, 1500, 512, 1, 0, T3_, T3_, 1);

    stats_pool<<<1500, 256>>>(a5, bn5_g, bn5_b, pool);

    dense_relu6<<<(B_ * 512 * 32 + 255) / 256, 256>>>(l1_w, l1_b, pool, y1, 512, 3000);
    bn_batch<<<(512 * 32 + 255) / 256, 256>>>(y1, bn6_g, bn6_b, y1, 512);

    dense_relu6<<<(B_ * 512 * 32 + 255) / 256, 256>>>(l2_w, l2_b, y1, y2, 512, 512);
    bn_batch<<<(512 * 32 + 255) / 256, 256>>>(y2, bn7_g, bn7_b, (float*)d_out, 512);
}

// round 12
// speedup vs baseline: 1.7464x; 1.0813x over previous
#include <cuda_runtime.h>
#include <math.h>

#define B_  32
#define T0_ 2048
#define T1_ 2044
#define T2_ 2040
#define T3_ 2034

// ---------------- scratch (device globals; no allocations allowed) ----------
__device__ float g_xT  [20   * B_ * T0_];
__device__ float g_act1[512  * B_ * T1_];
__device__ float g_act2[512  * B_ * T2_];
__device__ float g_act3[512  * B_ * T3_];
__device__ float g_act4[512  * B_ * T3_];
__device__ float g_act5[1500 * B_ * T3_];
__device__ float g_scl [1500];
__device__ float g_shf [1500];
__device__ __align__(16) uint2 g_wp[512 * 1536 / 2];  // packed bf16 hi/lo pairs [K/2][M]
__device__ float g_bp  [1500];
__device__ float g_pool[B_ * 3000];
__device__ float g_y1  [B_ * 512];
__device__ float g_y2  [B_ * 512];

// ---------------- transpose x[b][t][f] -> xT[f][b][t] -----------------------
__global__ void transpose_x(const float* __restrict__ x, float* __restrict__ xT) {
    int idx = blockIdx.x * blockDim.x + threadIdx.x;
    const int total = B_ * T0_ * 20;
    if (idx >= total) return;
    int f = idx % 20;
    int t = (idx / 20) % T0_;
    int b = idx / (20 * T0_);
    xT[((size_t)f * B_ + b) * T0_ + t] = x[idx];
}

// ---------------- BF16 split helpers -----------------------------------------
__device__ __forceinline__ void pack_split_bf16(float v0, float v1,
                                                unsigned &hi, unsigned &lo) {
    unsigned h;
    asm("cvt.rn.bf16x2.f32 %0, %1, %2;" : "=r"(h) : "f"(v1), "f"(v0));
    float h0 = __uint_as_float(h << 16);
    float h1 = __uint_as_float(h & 0xffff0000u);
    float l0 = v0 - h0;
    float l1 = v1 - h1;
    unsigned l;
    asm("cvt.rn.bf16x2.f32 %0, %1, %2;" : "=r"(l) : "f"(l1), "f"(l0));
    hi = h; lo = l;
}

// ---------------- weight prep: transpose + fold BN scale + bf16 split --------
// Wp[kp*M + m] = { packed bf16(hi of w[2kp],w[2kp+1]), packed bf16 residuals }
__global__ void prep_wp(const float* __restrict__ W, const float* __restrict__ scl,
                        uint2* __restrict__ Wp, int M, int K, int C, int hasAff)
{
    int idx = blockIdx.x * blockDim.x + threadIdx.x;
    int total = (K >> 1) * M;
    if (idx >= total) return;
    int kp = idx / M, m = idx - kp * M;
    int k0 = 2 * kp, k1 = 2 * kp + 1;
    float s0 = hasAff ? scl[k0 / C] : 1.f;
    float s1 = hasAff ? scl[k1 / C] : 1.f;
    float v0 = W[(size_t)m * K + k0] * s0;
    float v1 = W[(size_t)m * K + k1] * s1;
    unsigned h, l;
    pack_split_bf16(v0, v1, h, l);
    Wp[idx] = make_uint2(h, l);
}
__global__ void prep_bias(const float* __restrict__ W, const float* __restrict__ bias,
                          const float* __restrict__ shf, float* __restrict__ bp,
                          int M, int K, int C, int hasAff)
{
    int m    = blockIdx.x * (blockDim.x >> 5) + (threadIdx.x >> 5);
    int lane = threadIdx.x & 31;
    if (m >= M) return;
    float acc = 0.f;
    if (hasAff)
        for (int k = lane; k < K; k += 32) acc += W[(size_t)m * K + k] * shf[k / C];
#pragma unroll
    for (int off = 16; off; off >>= 1) acc += __shfl_xor_sync(0xffffffffu, acc, off);
    if (lane == 0) bp[m] = bias[m] + acc;
}

// ---------------- mma / cp.async helpers -------------------------------------
__device__ __forceinline__ void mma_bf16(float c[4],
                                         unsigned a0, unsigned a1, unsigned a2, unsigned a3,
                                         unsigned b0, unsigned b1) {
    asm("mma.sync.aligned.m16n8k16.row.col.f32.bf16.bf16.f32 "
        "{%0,%1,%2,%3}, {%4,%5,%6,%7}, {%8,%9}, {%0,%1,%2,%3};"
        : "+f"(c[0]), "+f"(c[1]), "+f"(c[2]), "+f"(c[3])
        : "r"(a0), "r"(a1), "r"(a2), "r"(a3), "r"(b0), "r"(b1));
}
__device__ __forceinline__ unsigned smem_u32(const void* p) {
    return (unsigned)__cvta_generic_to_shared(p);
}
__device__ __forceinline__ void cp16(unsigned dst, const void* src, int sbytes) {
    asm volatile("cp.async.ca.shared.global [%0], [%1], 16, %2;"
                 :: "r"(dst), "l"(src), "r"(sbytes));
}
__device__ __forceinline__ void cp4(unsigned dst, const float* src, int sbytes) {
    asm volatile("cp.async.ca.shared.global [%0], [%1], 4, %2;"
                 :: "r"(dst), "l"(src), "r"(sbytes));
}

// ---------------- fused splice + 1x1 conv GEMM -------------------------------
// 3xBF16 split-precision tensor-core GEMM (m16n8k16, fp32 accumulate).
// Block 128x128x16, 8 warps, warp tile 64x32.
// A operand: PRE-SPLIT packed bf16 hi/lo uint2 in smem -> LDS.64 fragment-ready.
// B operand: raw fp32 in smem, split+packed at fragment load.
#define TBM 128
#define TBN 128
#define TBK 16
#define KP  8         // kp rows per tile
#define PADA 4        // uint2 pad
#define PADB 4        // float pad

__global__ __launch_bounds__(256, 2)
void gemm_splice(const uint2* __restrict__ Wp, const float* __restrict__ bias,
                 const float* __restrict__ X, float* __restrict__ Y,
                 int M, int K, int C, int offStride,
                 int Tin, int Tout, int actMode)
{
    __shared__ uint2 As[2][KP][TBM + PADA];
    __shared__ float Bs[2][TBK][TBN + PADB];

    const int b     = blockIdx.z;
    const int m0    = blockIdx.y * TBM;
    const int tbase = blockIdx.x * TBN;
    const int tid   = threadIdx.x;

    const int lane  = tid & 31;
    const int warp  = tid >> 5;
    const int g     = lane >> 2;
    const int tg    = lane & 3;
    const int wm    = (warp & 1) * 64;
    const int wn    = (warp >> 1) * 32;

    const float* Xb = X + (size_t)b * Tin;
    const int K2 = K >> 1;

    float acc[4][4][4];
#pragma unroll
    for (int mi = 0; mi < 4; mi++)
#pragma unroll
        for (int ni = 0; ni < 4; ni++)
#pragma unroll
            for (int r = 0; r < 4; r++) acc[mi][ni][r] = 0.f;

    // producer mapping
    const int aKp = tid >> 5;            // 0..7 kp row
    const int aM0 = (tid & 31) * 4;      // uint2 col 0..124
    const int bRow  = tid >> 4;          // 0..15
    const int bCol0 = (tid & 15) * 8;

    const int nT = (K + TBK - 1) / TBK;

#define PREFETCH(K0, BUF)                                                          \
    {                                                                              \
        int kp = (K0) / 2 + aKp;                                                   \
        const uint2* asrc = Wp + (size_t)kp * M + m0 + aM0;                        \
        int av = (kp < K2) ? (M - (m0 + aM0)) : 0;                                 \
        int s0 = min(max(av, 0), 2) * 8;                                           \
        int s1 = min(max(av - 2, 0), 2) * 8;                                       \
        cp16(smem_u32(&As[BUF][aKp][aM0]),     asrc,     s0);                      \
        cp16(smem_u32(&As[BUF][aKp][aM0 + 2]), asrc + 2, s1);                      \
        int kB = (K0) + bRow;                                                      \
        bool kv = (kB < K);                                                        \
        int f = 0, off = 0;                                                        \
        if (kv) { f = kB / C; off = (kB - f * C) * offStride; }                    \
        const float* bsrc = Xb + (size_t)f * (B_ * (size_t)Tin) + off + tbase + bCol0; \
        _Pragma("unroll")                                                          \
        for (int j = 0; j < 8; j++) {                                              \
            int t = tbase + bCol0 + j;                                             \
            cp4(smem_u32(&Bs[BUF][bRow][bCol0 + j]), bsrc + j,                     \
                (kv && t < Tout) ? 4 : 0);                                         \
        }                                                                          \
        asm volatile("cp.async.commit_group;");                                    \
    }

    PREFETCH(0, 0);
    asm volatile("cp.async.wait_group 0;");
    __syncthreads();

    for (int it = 0; it < nT; it++) {
        const int buf = it & 1;
        if (it + 1 < nT) PREFETCH((it + 1) * TBK, buf ^ 1);

        unsigned afh[4][4], afl[4][4], bfh[4][2], bfl[4][2];
#pragma unroll
        for (int mi = 0; mi < 4; mi++) {
            int m = wm + mi * 16 + g;
            uint2 q0 = As[buf][tg    ][m    ];
            uint2 q1 = As[buf][tg    ][m + 8];
            uint2 q2 = As[buf][tg + 4][m    ];
            uint2 q3 = As[buf][tg + 4][m + 8];
            afh[mi][0] = q0.x; afl[mi][0] = q0.y;
            afh[mi][1] = q1.x; afl[mi][1] = q1.y;
            afh[mi][2] = q2.x; afl[mi][2] = q2.y;
            afh[mi][3] = q3.x; afl[mi][3] = q3.y;
        }
#pragma unroll
        for (int ni = 0; ni < 4; ni++) {
            int n = wn + ni * 8 + g;
            pack_split_bf16(Bs[buf][2*tg    ][n], Bs[buf][2*tg + 1][n],
                            bfh[ni][0], bfl[ni][0]);
            pack_split_bf16(Bs[buf][2*tg + 8][n], Bs[buf][2*tg + 9][n],
                            bfh[ni][1], bfl[ni][1]);
        }
#pragma unroll
        for (int mi = 0; mi < 4; mi++)
#pragma unroll
            for (int ni = 0; ni < 4; ni++) {
                mma_bf16(acc[mi][ni], afh[mi][0], afh[mi][1], afh[mi][2], afh[mi][3],
                         bfh[ni][0], bfh[ni][1]);
                mma_bf16(acc[mi][ni], afh[mi][0], afh[mi][1], afh[mi][2], afh[mi][3],
                         bfl[ni][0], bfl[ni][1]);
                mma_bf16(acc[mi][ni], afl[mi][0], afl[mi][1], afl[mi][2], afl[mi][3],
                         bfh[ni][0], bfh[ni][1]);
            }

        if (it + 1 < nT) asm volatile("cp.async.wait_group 0;");
        __syncthreads();
    }

    // ---- epilogue: bias + activation, write [M][B][Tout] ----
    const size_t strideY = (size_t)B_ * Tout;
#pragma unroll
    for (int mi = 0; mi < 4; mi++) {
        int mA = m0 + wm + mi * 16 + g;
        int mB = mA + 8;
        float biA = (mA < M) ? bias[mA] : 0.f;
        float biB = (mB < M) ? bias[mB] : 0.f;
#pragma unroll
        for (int ni = 0; ni < 4; ni++) {
            int t = tbase + wn + ni * 8 + tg * 2;
            if (t >= Tout) continue;
            if (mA < M) {
                float2 v;
                v.x = fmaxf(acc[mi][ni][0] + biA, 0.f);
                v.y = fmaxf(acc[mi][ni][1] + biA, 0.f);
                if (actMode) { v.x = fminf(v.x, 6.f); v.y = fminf(v.y, 6.f); }
                *(float2*)&Y[(size_t)mA * strideY + (size_t)b * Tout + t] = v;
            }
            if (mB < M) {
                float2 v;
                v.x = fmaxf(acc[mi][ni][2] + biB, 0.f);
                v.y = fmaxf(acc[mi][ni][3] + biB, 0.f);
                if (actMode) { v.x = fminf(v.x, 6.f); v.y = fminf(v.y, 6.f); }
                *(float2*)&Y[(size_t)mB * strideY + (size_t)b * Tout + t] = v;
            }
        }
    }
#undef PREFETCH
}

// ---------------- per-channel batch-norm stats (over B*T) -------------------
__global__ void channel_stats(const float* __restrict__ Y, int N,
                              const float* __restrict__ gam, const float* __restrict__ bet,
                              float* __restrict__ scl, float* __restrict__ shf)
{
    int c = blockIdx.x;
    const float4* p = (const float4*)(Y + (size_t)c * N);
    int n4 = N >> 2;
    float s1 = 0.f, s2 = 0.f;
    for (int i = threadIdx.x; i < n4; i += blockDim.x) {
        float4 v = p[i];
        s1 += v.x + v.y + v.z + v.w;
        s2 += v.x*v.x + v.y*v.y + v.z*v.z + v.w*v.w;
    }
    __shared__ float r1[256], r2[256];
    r1[threadIdx.x] = s1; r2[threadIdx.x] = s2;
    __syncthreads();
    for (int s = 128; s > 0; s >>= 1) {
        if (threadIdx.x < s) {
            r1[threadIdx.x] += r1[threadIdx.x + s];
            r2[threadIdx.x] += r2[threadIdx.x + s];
        }
        __syncthreads();
    }
    if (threadIdx.x == 0) {
        float m   = r1[0] / (float)N;
        float var = r2[0] / (float)N - m * m;
        float inv = rsqrtf(var + 1e-5f);
        float g   = gam ? gam[c] : 1.f;
        float be  = bet ? bet[c] : 0.f;
        float A   = g * inv;
        scl[c] = A;
        shf[c] = be - m * A;
    }
}

// ---------------- fused bn5 stats + pooled mean/std --------------------------
__global__ void stats_pool(const float* __restrict__ A,
                           const float* __restrict__ gam, const float* __restrict__ bet,
                           float* __restrict__ P)
{
    int c   = blockIdx.x;
    int tid = threadIdx.x;
    int bb  = tid >> 3;
    int sub = tid & 7;
    const float* p = A + ((size_t)c * B_ + bb) * T3_;
    float s1 = 0.f, s2 = 0.f;
    const int n2 = T3_ >> 1;
    for (int i = sub; i < n2; i += 8) {
        float2 v = *(const float2*)(p + 2 * i);
        s1 += v.x + v.y;
        s2 += v.x * v.x + v.y * v.y;
    }
    __shared__ float r1[256], r2[256];
    r1[tid] = s1; r2[tid] = s2;
    __syncthreads();
    if (sub < 4) { r1[tid] += r1[tid + 4]; r2[tid] += r2[tid + 4]; }
    __syncthreads();
    if (sub < 2) { r1[tid] += r1[tid + 2]; r2[tid] += r2[tid + 2]; }
    __syncthreads();
    if (sub == 0) { r1[tid] += r1[tid + 1]; r2[tid] += r2[tid + 1]; }
    __syncthreads();
    __shared__ float shA, shD;
    if (tid == 0) {
        float t1 = 0.f, t2 = 0.f;
        for (int i = 0; i < 32; i++) { t1 += r1[i * 8]; t2 += r2[i * 8]; }
        float m   = t1 / (float)(B_ * T3_);
        float var = t2 / (float)(B_ * T3_) - m * m;
        float inv = rsqrtf(var + 1e-5f);
        float Aa  = gam[c] * inv;
        shA = Aa;
        shD = bet[c] - m * Aa;
    }
    __syncthreads();
    if (sub == 0) {
        float m   = r1[tid] / (float)T3_;
        float var = (r2[tid] - (float)T3_ * m * m) / (float)(T3_ - 1);
        P[bb * 3000 + c]        = shA * m + shD;
        P[bb * 3000 + 1500 + c] = fabsf(shA) * sqrtf(fmaxf(var, 0.f));
    }
}

// ---------------- dense + relu6 (one warp per output) -----------------------
__global__ void dense_relu6(const float* __restrict__ W, const float* __restrict__ bias,
                            const float* __restrict__ X, float* __restrict__ Y,
                            int M, int K)
{
    int gw   = (blockIdx.x * blockDim.x + threadIdx.x) >> 5;
    int lane = threadIdx.x & 31;
    if (gw >= B_ * M) return;
    int b = gw / M, o = gw - b * M;
    const float* w = W + (size_t)o * K;
    const float* x = X + (size_t)b * K;
    float s = 0.f;
    for (int k = lane; k < K; k += 32) s += w[k] * x[k];
#pragma unroll
    for (int off = 16; off; off >>= 1) s += __shfl_xor_sync(0xffffffffu, s, off);
    if (lane == 0) {
        float v = s + bias[o];
        Y[(size_t)b * M + o] = fminf(fmaxf(v, 0.f), 6.f);
    }
}

// ---------------- batch-norm over batch dim (B=32 == warp) ------------------
__global__ void bn_batch(const float* __restrict__ Y, const float* __restrict__ gam,
                         const float* __restrict__ bet, float* __restrict__ Out, int M)
{
    int o    = (blockIdx.x * blockDim.x + threadIdx.x) >> 5;
    int lane = threadIdx.x & 31;
    if (o >= M) return;
    float v  = Y[(size_t)lane * M + o];
    float s1 = v, s2 = v * v;
#pragma unroll
    for (int off = 16; off; off >>= 1) {
        s1 += __shfl_xor_sync(0xffffffffu, s1, off);
        s2 += __shfl_xor_sync(0xffffffffu, s2, off);
    }
    float m   = s1 * (1.f / 32.f);
    float var = s2 * (1.f / 32.f) - m * m;
    float r   = rsqrtf(var + 1e-5f);
    Out[(size_t)lane * M + o] = (v - m) * r * gam[o] + bet[o];
}

// ---------------- launch ----------------------------------------------------
extern "C" void kernel_launch(void* const* d_in, const int* in_sizes, int n_in,
                              void* d_out, int out_size)
{
    const float* x     = (const float*)d_in[0];
    const float* h1_w  = (const float*)d_in[1];
    const float* h1_b  = (const float*)d_in[2];
    const float* h2_w  = (const float*)d_in[3];
    const float* h2_b  = (const float*)d_in[4];
    const float* bn2_g = (const float*)d_in[5];
    const float* bn2_b = (const float*)d_in[6];
    const float* h3_w  = (const float*)d_in[7];
    const float* h3_b  = (const float*)d_in[8];
    const float* bn3_g = (const float*)d_in[9];
    const float* bn3_b = (const float*)d_in[10];
    const float* h4_w  = (const float*)d_in[11];
    const float* h4_b  = (const float*)d_in[12];
    const float* bn4_g = (const float*)d_in[13];
    const float* bn4_b = (const float*)d_in[14];
    const float* h5_w  = (const float*)d_in[15];
    const float* h5_b  = (const float*)d_in[16];
    const float* bn5_g = (const float*)d_in[17];
    const float* bn5_b = (const float*)d_in[18];
    const float* l1_w  = (const float*)d_in[19];
    const float* l1_b  = (const float*)d_in[20];
    const float* bn6_g = (const float*)d_in[21];
    const float* bn6_b = (const float*)d_in[22];
    const float* l2_w  = (const float*)d_in[23];
    const float* l2_b  = (const float*)d_in[24];
    const float* bn7_g = (const float*)d_in[25];
    const float* bn7_b = (const float*)d_in[26];

    float *xT, *a1, *a2, *a3, *a4, *a5, *scl, *shf, *bp, *pool, *y1, *y2;
    uint2* wp;
    cudaGetSymbolAddress((void**)&xT,   g_xT);
    cudaGetSymbolAddress((void**)&a1,   g_act1);
    cudaGetSymbolAddress((void**)&a2,   g_act2);
    cudaGetSymbolAddress((void**)&a3,   g_act3);
    cudaGetSymbolAddress((void**)&a4,   g_act4);
    cudaGetSymbolAddress((void**)&a5,   g_act5);
    cudaGetSymbolAddress((void**)&scl,  g_scl);
    cudaGetSymbolAddress((void**)&shf,  g_shf);
    cudaGetSymbolAddress((void**)&wp,   g_wp);
    cudaGetSymbolAddress((void**)&bp,   g_bp);
    cudaGetSymbolAddress((void**)&pool, g_pool);
    cudaGetSymbolAddress((void**)&y1,   g_y1);
    cudaGetSymbolAddress((void**)&y2,   g_y2);

    const int N1 = B_ * T1_;
    const int N2 = B_ * T2_;
    const int N3 = B_ * T3_;

    transpose_x<<<(B_ * T0_ * 20 + 255) / 256, 256>>>(x, xT);

    // Layer 1
    prep_wp<<<(50 * 512 + 255) / 256, 256>>>(h1_w, nullptr, wp, 512, 100, 5, 0);
    prep_bias<<<(512 + 7) / 8, 256>>>(h1_w, h1_b, nullptr, bp, 512, 100, 5, 0);
    gemm_splice<<<dim3((T1_ + 127) / 128, 4, B_), 256>>>(
        wp, bp, xT, a1, 512, 100, 5, 1, T0_, T1_, 0);
    channel_stats<<<512, 256>>>(a1, N1, nullptr, nullptr, scl, shf);

    // Layer 2
    prep_wp<<<(768 * 512 + 255) / 256, 256>>>(h2_w, scl, wp, 512, 1536, 3, 1);
    prep_bias<<<(512 + 7) / 8, 256>>>(h2_w, h2_b, shf, bp, 512, 1536, 3, 1);
    gemm_splice<<<dim3((T2_ + 127) / 128, 4, B_), 256>>>(
        wp, bp, a1, a2, 512, 1536, 3, 2, T1_, T2_, 0);
    channel_stats<<<512, 256>>>(a2, N2, bn2_g, bn2_b, scl, shf);

    // Layer 3
    prep_wp<<<(768 * 512 + 255) / 256, 256>>>(h3_w, scl, wp, 512, 1536, 3, 1);
    prep_bias<<<(512 + 7) / 8, 256>>>(h3_w, h3_b, shf, bp, 512, 1536, 3, 1);
    gemm_splice<<<dim3((T3_ + 127) / 128, 4, B_), 256>>>(
        wp, bp, a2, a3, 512, 1536, 3, 3, T2_, T3_, 0);
    channel_stats<<<512, 256>>>(a3, N3, bn3_g, bn3_b, scl, shf);

    // Layer 4
    prep_wp<<<(256 * 512 + 255) / 256, 256>>>(h4_w, scl, wp, 512, 512, 1, 1);
    prep_bias<<<(512 + 7) / 8, 256>>>(h4_w, h4_b, shf, bp, 512, 512, 1, 1);
    gemm_splice<<<dim3((T3_ + 127) / 128, 4, B_), 256>>>(
        wp, bp, a3, a4, 512, 512, 1, 0, T3_, T3_, 1);
    channel_stats<<<512, 256>>>(a4, N3, bn4_g, bn4_b, scl, shf);

    // Layer 5
    prep_wp<<<(256 * 1500 + 255) / 256, 256>>>(h5_w, scl, wp, 1500, 512, 1, 1);
    prep_bias<<<(1500 + 7) / 8, 256>>>(h5_w, h5_b, shf, bp, 1500, 512, 1, 1);
    gemm_splice<<<dim3((T3_ + 127) / 128, 12, B_), 256>>>(
        wp, bp, a4, a5, 1500, 512, 1, 0, T3_, T3_, 1);

    stats_pool<<<1500, 256>>>(a5, bn5_g, bn5_b, pool);

    dense_relu6<<<(B_ * 512 * 32 + 255) / 256, 256>>>(l1_w, l1_b, pool, y1, 512, 3000);
    bn_batch<<<(512 * 32 + 255) / 256, 256>>>(y1, bn6_g, bn6_b, y1, 512);

    dense_relu6<<<(B_ * 512 * 32 + 255) / 256, 256>>>(l2_w, l2_b, y1, y2, 512, 512);
    bn_batch<<<(512 * 32 + 255) / 256, 256>>>(y2, bn7_g, bn7_b, (float*)d_out, 512);
}